// round 13
// baseline (speedup 1.0000x reference)
#include <cuda_runtime.h>
#include <cuda_bf16.h>
#include <cuda_fp16.h>
#include <math.h>
#include <stdint.h>

#define NTOK 4096
#define DIM  1024
#define NEXP 8
#define TM   128
#define TN   128
#define KC   64                      // K elems per pipeline chunk
#define NCH  (DIM / KC)              // 16
#define MAX_TILES (NTOK / TM + NEXP) // 40

// padded SMEM row: 64 fp16 data + 8 pad = 72 elems = 144 bytes (conflict-free)
#define SROW 144
#define MAT_BYTES   (128 * SROW)         // 18432
#define STAGE_BYTES (2 * MAT_BYTES)      // 36864 (A, B)
#define NSTAGE 3
#define SMEM_BYTES  (NSTAGE * STAGE_BYTES)   // 110592

#define GEMM_CTAS (2 * 148)

// ---------------- device scratch ----------------
__device__ float g_weight[NTOK];
__device__ int   g_expert[NTOK];
__device__ int   g_fill[NEXP];
__device__ int   g_offsets[NEXP + 1];
__device__ int   g_sorted[NTOK];
__device__ int2  g_tiles[MAX_TILES];
__device__ int   g_num_tiles;
__device__ int   g_ticket;
__device__ __half g_xh[NTOK * DIM];      // token-indexed (unsorted) fp16 x
__device__ __half g_wh[NEXP * DIM * DIM];

// ---------------- PTX helpers (base compute_103 only) ----------------
__device__ __forceinline__ uint32_t smem_u32(const void* p) {
    uint32_t a;
    asm("{ .reg .u64 t; cvta.to.shared.u64 t, %1; cvt.u32.u64 %0, t; }" : "=r"(a) : "l"(p));
    return a;
}
#define CP_ASYNC16(dst, src) \
    asm volatile("cp.async.cg.shared.global [%0], [%1], 16;" :: "r"(dst), "l"(src) : "memory")
#define CP_COMMIT() asm volatile("cp.async.commit_group;" ::: "memory")
#define CP_WAIT(n)  asm volatile("cp.async.wait_group %0;" :: "n"(n) : "memory")

#define LDSM_X4(r0, r1, r2, r3, addr) \
    asm volatile("ldmatrix.sync.aligned.m8n8.x4.shared.b16 {%0,%1,%2,%3}, [%4];" \
                 : "=r"(r0), "=r"(r1), "=r"(r2), "=r"(r3) : "r"(addr))

#define MMA_F16(c, a, b) \
    asm volatile("mma.sync.aligned.m16n8k16.row.col.f32.f16.f16.f32 " \
                 "{%0,%1,%2,%3}, {%4,%5,%6,%7}, {%8,%9}, {%0,%1,%2,%3};" \
                 : "+f"((c)[0]), "+f"((c)[1]), "+f"((c)[2]), "+f"((c)[3]) \
                 : "r"((a)[0]), "r"((a)[1]), "r"((a)[2]), "r"((a)[3]), \
                   "r"((b)[0]), "r"((b)[1]))

// ---------------- small kernels ----------------
// router: expert + weight per token, AND fp32->fp16 conversion of x (fused)
__global__ void k_router(const float* __restrict__ x,
                         const float* __restrict__ rw,
                         const float* __restrict__ rb) {
    int warp = (blockIdx.x * blockDim.x + threadIdx.x) >> 5;
    int lane = threadIdx.x & 31;
    if (warp >= NTOK) return;
    const float4* xr = (const float4*)(x + (size_t)warp * DIM);
    uint2* xo = (uint2*)(g_xh + (size_t)warp * DIM);
    float acc[NEXP];
#pragma unroll
    for (int e = 0; e < NEXP; e++) acc[e] = 0.f;
#pragma unroll
    for (int it = 0; it < DIM / 4 / 32; it++) {
        int i = lane + it * 32;
        float4 xv = xr[i];
        union { __half h[4]; uint2 u; } hv;
        hv.h[0] = __float2half(xv.x);
        hv.h[1] = __float2half(xv.y);
        hv.h[2] = __float2half(xv.z);
        hv.h[3] = __float2half(xv.w);
        xo[i] = hv.u;
#pragma unroll
        for (int e = 0; e < NEXP; e++) {
            float4 wv = ((const float4*)(rw + e * DIM))[i];
            acc[e] += xv.x * wv.x + xv.y * wv.y + xv.z * wv.z + xv.w * wv.w;
        }
    }
#pragma unroll
    for (int e = 0; e < NEXP; e++)
#pragma unroll
        for (int o = 16; o > 0; o >>= 1)
            acc[e] += __shfl_xor_sync(0xFFFFFFFFu, acc[e], o);
    if (lane == 0) {
        float best = -1e30f; int bi = 0;
#pragma unroll
        for (int e = 0; e < NEXP; e++) {
            float l = acc[e] + rb[e];
            if (l > best) { best = l; bi = e; }
        }
        float s = 0.f;
#pragma unroll
        for (int e = 0; e < NEXP; e++) s += expf(acc[e] + rb[e] - best);
        g_weight[warp] = 1.f / s;
        g_expert[warp] = bi;
    }
}

// fused init + histogram + scan + tile list (single block, 1024 threads)
__global__ void k_histscan() {
    __shared__ int h[NEXP];
    int tid = threadIdx.x;
    if (tid < NEXP) { h[tid] = 0; g_fill[tid] = 0; }
    if (tid == 0) g_ticket = 0;
    __syncthreads();
#pragma unroll
    for (int i = 0; i < NTOK / 1024; i++)
        atomicAdd(&h[g_expert[tid + i * 1024]], 1);
    __syncthreads();
    if (tid == 0) {
        int off = 0, nt = 0;
        for (int e = 0; e < NEXP; e++) {
            g_offsets[e] = off;
            int c = h[e];
            for (int s = 0; s < c; s += TM) g_tiles[nt++] = make_int2(e, off + s);
            off += c;
        }
        g_offsets[NEXP] = off;
        g_num_tiles = nt;
    }
}

// position assignment via ballot aggregation (16 blocks x 256; 8 atomics/block)
__global__ void k_pos() {
    __shared__ int warp_cnt[8][NEXP];
    __shared__ int warp_base[8][NEXP];
    int t = blockIdx.x * blockDim.x + threadIdx.x;
    int e = g_expert[t];
    int lane = threadIdx.x & 31, w = threadIdx.x >> 5;
    int lane_rank = 0;
#pragma unroll
    for (int ee = 0; ee < NEXP; ee++) {
        unsigned m = __ballot_sync(0xFFFFFFFFu, e == ee);
        if (e == ee) lane_rank = __popc(m & ((1u << lane) - 1));
        if (lane == 0) warp_cnt[w][ee] = __popc(m);
    }
    __syncthreads();
    if (threadIdx.x < NEXP) {
        int ee = threadIdx.x;
        int sum = 0, pre[8];
#pragma unroll
        for (int ww = 0; ww < 8; ww++) { pre[ww] = sum; sum += warp_cnt[ww][ee]; }
        int base = atomicAdd(&g_fill[ee], sum);
#pragma unroll
        for (int ww = 0; ww < 8; ww++) warp_base[ww][ee] = base + pre[ww];
    }
    __syncthreads();
    int pos = g_offsets[e] + warp_base[w][e] + lane_rank;
    g_sorted[pos] = t;
}

// grid-stride weight conversion
__global__ void k_prep_w(const float* __restrict__ ew) {
    const size_t total = (size_t)NEXP * DIM * DIM / 4;   // float4 count
    size_t stride = (size_t)gridDim.x * blockDim.x;
    for (size_t i4 = (size_t)blockIdx.x * blockDim.x + threadIdx.x; i4 < total; i4 += stride) {
        float4 v = ((const float4*)ew)[i4];
        union { __half h[4]; uint2 u; } h4;
        h4.h[0] = __float2half(v.x);
        h4.h[1] = __float2half(v.y);
        h4.h[2] = __float2half(v.z);
        h4.h[3] = __float2half(v.w);
        ((uint2*)g_wh)[i4] = h4.u;
    }
}

// ---------------- persistent mma.sync grouped GEMM (128x128, padded, hoisted gather) ----------------
__global__ void __launch_bounds__(256, 2) k_gemm(const float* __restrict__ eb,
                                                 float* __restrict__ out) {
    extern __shared__ char smem[];
    uint32_t sb = smem_u32(smem);
    __shared__ int   s_job;
    __shared__ int   s_tok[TM];
    __shared__ float s_w[TM];

    int tid = threadIdx.x;
    int wid = tid >> 5;
    int lane = tid & 31;
    int warp_m = wid & 3;    // 4 slabs of 32 rows
    int warp_n = wid >> 2;   // 2 slabs of 64 cols

    uint32_t aoff = (uint32_t)((warp_m * 32 + (lane & 15)) * SROW + (lane >> 4) * 16);
    uint32_t boff = (uint32_t)((warp_n * 64 + ((lane >> 4) << 3) + (lane & 7)) * SROW
                               + ((lane >> 3) & 1) * 16);

    // cp.async geometry: thread covers 4 segs of A row (tid>>1) and B row (tid>>1)
    int rload = tid >> 1;            // 0..127
    int sbase = (tid & 1) * 4;       // 0 or 4
    uint32_t dA = (uint32_t)(rload * SROW + sbase * 16);
    uint32_t dB = (uint32_t)(MAT_BYTES + rload * SROW + sbase * 16);

    for (;;) {
        if (tid == 0) s_job = atomicAdd(&g_ticket, 1);
        __syncthreads();
        int job = s_job;
        int njobs = g_num_tiles * (DIM / TN);
        if (job >= njobs) return;

        int nb   = job & 7;          // DIM/TN == 8
        int tile = job >> 3;
        int2 td = g_tiles[tile];
        int e = td.x, row0 = td.y;
        int segend = g_offsets[e + 1];
        int n0 = nb * TN;

        if (tid < TM) {
            int r = row0 + tid;
            int tok = (r < segend) ? g_sorted[r] : -1;
            s_tok[tid] = tok;
            s_w[tid]   = (tok >= 0) ? g_weight[tok] : 0.f;
        }
        __syncthreads();

        // hoisted gather pointers (computed once per job)
        int tA = s_tok[rload]; if (tA < 0) tA = 0;
        const __half* pA = g_xh + (size_t)tA * DIM + sbase * 8;
        const __half* pB = g_wh + (size_t)(e * DIM + n0 + rload) * DIM + sbase * 8;

        float c[2][8][4];
#pragma unroll
        for (int mt = 0; mt < 2; mt++)
#pragma unroll
            for (int nt = 0; nt < 8; nt++)
#pragma unroll
                for (int j = 0; j < 4; j++) c[mt][nt][j] = 0.f;

        auto issue = [&](int ch, int st) {
            int k0 = ch * KC;
            uint32_t stb = sb + st * STAGE_BYTES;
#pragma unroll
            for (int j = 0; j < 4; j++) CP_ASYNC16(stb + dA + j * 16, pA + k0 + j * 8);
#pragma unroll
            for (int j = 0; j < 4; j++) CP_ASYNC16(stb + dB + j * 16, pB + k0 + j * 8);
            CP_COMMIT();
        };

        issue(0, 0); issue(1, 1); issue(2, 2);

        for (int ch = 0; ch < NCH; ch++) {
            int st = ch % NSTAGE;
            int rem = NCH - 1 - ch;
            if (rem >= 2) CP_WAIT(2);
            else if (rem == 1) CP_WAIT(1);
            else CP_WAIT(0);
            __syncthreads();

            uint32_t sA = sb + st * STAGE_BYTES;
            uint32_t sB = sA + MAT_BYTES;
#pragma unroll
            for (int ks = 0; ks < 4; ks++) {
                uint32_t kb = ks * 32;           // 16 elems * 2B
                uint32_t a[2][4], b[8][2];
#pragma unroll
                for (int mt = 0; mt < 2; mt++) {
                    uint32_t aa = sA + mt * (16 * SROW) + aoff + kb;
                    LDSM_X4(a[mt][0], a[mt][1], a[mt][2], a[mt][3], aa);
                }
#pragma unroll
                for (int p = 0; p < 4; p++) {
                    uint32_t ba = sB + p * (16 * SROW) + boff + kb;
                    LDSM_X4(b[p * 2][0], b[p * 2][1], b[p * 2 + 1][0], b[p * 2 + 1][1], ba);
                }
#pragma unroll
                for (int mt = 0; mt < 2; mt++)
#pragma unroll
                    for (int nt = 0; nt < 8; nt++)
                        MMA_F16(c[mt][nt], a[mt], b[nt]);
            }
            __syncthreads();
            if (ch + NSTAGE < NCH) issue(ch + NSTAGE, st);
        }

        // ---------------- epilogue ----------------
        int ncol_base = n0 + warp_n * 64 + (lane & 3) * 2;
#pragma unroll
        for (int mt = 0; mt < 2; mt++) {
#pragma unroll
            for (int half = 0; half < 2; half++) {
                int rl = warp_m * 32 + mt * 16 + (lane >> 2) + half * 8;
                int tok = s_tok[rl];
                if (tok < 0) continue;
                float wt = s_w[rl];
                float* orow = out + (size_t)tok * DIM;
#pragma unroll
                for (int nt = 0; nt < 8; nt++) {
                    int nc = ncol_base + nt * 8;
                    float2 b2 = *(const float2*)(eb + (size_t)e * DIM + nc);
                    float2 r2;
                    r2.x = (c[mt][nt][half * 2 + 0] + b2.x) * wt;
                    r2.y = (c[mt][nt][half * 2 + 1] + b2.y) * wt;
                    *(float2*)(orow + nc) = r2;
                }
            }
        }
        __syncthreads();   // protect s_job / s_tok before next job
    }
}

// ---------------- launch ----------------
extern "C" void kernel_launch(void* const* d_in, const int* in_sizes, int n_in,
                              void* d_out, int out_size) {
    const float* x  = (const float*)d_in[0];
    const float* rw = (const float*)d_in[1];
    const float* rb = (const float*)d_in[2];
    const float* ew = (const float*)d_in[3];
    const float* eb = (const float*)d_in[4];
    float* out = (float*)d_out;

    cudaFuncSetAttribute(k_gemm, cudaFuncAttributeMaxDynamicSharedMemorySize, SMEM_BYTES);

    k_router<<<(NTOK * 32) / 256, 256>>>(x, rw, rb);
    k_histscan<<<1, 1024>>>();
    k_pos<<<NTOK / 256, 256>>>();
    k_prep_w<<<8 * 148, 256>>>(ew);
    k_gemm<<<GEMM_CTAS, 256, SMEM_BYTES>>>(eb, out);
}

// round 14
// speedup vs baseline: 1.7023x; 1.7023x over previous
#include <cuda_runtime.h>
#include <cuda_bf16.h>
#include <cuda_fp16.h>
#include <math.h>
#include <stdint.h>

#define NTOK 4096
#define DIM  1024
#define NEXP 8
#define TM   128
#define TN   128
#define KC   64                      // K elems per pipeline chunk
#define NCH  (DIM / KC)              // 16
#define MAX_TILES (NTOK / TM + NEXP) // 40

// padded SMEM row: 64 fp16 data + 8 pad = 72 elems = 144 bytes (conflict-free)
#define SROW 144
#define MAT_BYTES   (128 * SROW)         // 18432
#define STAGE_BYTES (2 * MAT_BYTES)      // 36864 (A, B)
#define NSTAGE 3
#define SMEM_BYTES  (NSTAGE * STAGE_BYTES)   // 110592

#define GEMM_CTAS (2 * 148)

// ---------------- device scratch ----------------
__device__ float g_weight[NTOK];
__device__ int   g_expert[NTOK];
__device__ int   g_fill[NEXP];
__device__ int   g_offsets[NEXP + 1];
__device__ int   g_sorted[NTOK];
__device__ int2  g_tiles[MAX_TILES];
__device__ int   g_num_tiles;
__device__ int   g_ticket;
__device__ __half g_xh[NTOK * DIM];          // token-indexed fp16 x (from router)
__device__ __half g_xs[(NTOK + TM) * DIM];   // expert-sorted fp16 x (GEMM A operand)
__device__ __half g_wh[NEXP * DIM * DIM];

// ---------------- PTX helpers (base compute_103 only) ----------------
__device__ __forceinline__ uint32_t smem_u32(const void* p) {
    uint32_t a;
    asm("{ .reg .u64 t; cvta.to.shared.u64 t, %1; cvt.u32.u64 %0, t; }" : "=r"(a) : "l"(p));
    return a;
}
#define CP_ASYNC16(dst, src) \
    asm volatile("cp.async.cg.shared.global [%0], [%1], 16;" :: "r"(dst), "l"(src) : "memory")
#define CP_COMMIT() asm volatile("cp.async.commit_group;" ::: "memory")
#define CP_WAIT(n)  asm volatile("cp.async.wait_group %0;" :: "n"(n) : "memory")

#define LDSM_X4(r0, r1, r2, r3, addr) \
    asm volatile("ldmatrix.sync.aligned.m8n8.x4.shared.b16 {%0,%1,%2,%3}, [%4];" \
                 : "=r"(r0), "=r"(r1), "=r"(r2), "=r"(r3) : "r"(addr))

#define MMA_F16(c, a, b) \
    asm volatile("mma.sync.aligned.m16n8k16.row.col.f32.f16.f16.f32 " \
                 "{%0,%1,%2,%3}, {%4,%5,%6,%7}, {%8,%9}, {%0,%1,%2,%3};" \
                 : "+f"((c)[0]), "+f"((c)[1]), "+f"((c)[2]), "+f"((c)[3]) \
                 : "r"((a)[0]), "r"((a)[1]), "r"((a)[2]), "r"((a)[3]), \
                   "r"((b)[0]), "r"((b)[1]))

// ---------------- small kernels ----------------
// router: expert + weight per token, AND fp32->fp16 conversion of x (fused)
__global__ void k_router(const float* __restrict__ x,
                         const float* __restrict__ rw,
                         const float* __restrict__ rb) {
    int warp = (blockIdx.x * blockDim.x + threadIdx.x) >> 5;
    int lane = threadIdx.x & 31;
    if (warp >= NTOK) return;
    const float4* xr = (const float4*)(x + (size_t)warp * DIM);
    uint2* xo = (uint2*)(g_xh + (size_t)warp * DIM);
    float acc[NEXP];
#pragma unroll
    for (int e = 0; e < NEXP; e++) acc[e] = 0.f;
#pragma unroll
    for (int it = 0; it < DIM / 4 / 32; it++) {
        int i = lane + it * 32;
        float4 xv = xr[i];
        union { __half h[4]; uint2 u; } hv;
        hv.h[0] = __float2half(xv.x);
        hv.h[1] = __float2half(xv.y);
        hv.h[2] = __float2half(xv.z);
        hv.h[3] = __float2half(xv.w);
        xo[i] = hv.u;
#pragma unroll
        for (int e = 0; e < NEXP; e++) {
            float4 wv = ((const float4*)(rw + e * DIM))[i];
            acc[e] += xv.x * wv.x + xv.y * wv.y + xv.z * wv.z + xv.w * wv.w;
        }
    }
#pragma unroll
    for (int e = 0; e < NEXP; e++)
#pragma unroll
        for (int o = 16; o > 0; o >>= 1)
            acc[e] += __shfl_xor_sync(0xFFFFFFFFu, acc[e], o);
    if (lane == 0) {
        float best = -1e30f; int bi = 0;
#pragma unroll
        for (int e = 0; e < NEXP; e++) {
            float l = acc[e] + rb[e];
            if (l > best) { best = l; bi = e; }
        }
        float s = 0.f;
#pragma unroll
        for (int e = 0; e < NEXP; e++) s += expf(acc[e] + rb[e] - best);
        g_weight[warp] = 1.f / s;
        g_expert[warp] = bi;
    }
}

// fused init + histogram + scan + tile list (single block, 1024 threads)
__global__ void k_histscan() {
    __shared__ int h[NEXP];
    int tid = threadIdx.x;
    if (tid < NEXP) { h[tid] = 0; g_fill[tid] = 0; }
    if (tid == 0) g_ticket = 0;
    __syncthreads();
#pragma unroll
    for (int i = 0; i < NTOK / 1024; i++)
        atomicAdd(&h[g_expert[tid + i * 1024]], 1);
    __syncthreads();
    if (tid == 0) {
        int off = 0, nt = 0;
        for (int e = 0; e < NEXP; e++) {
            g_offsets[e] = off;
            int c = h[e];
            for (int s = 0; s < c; s += TM) g_tiles[nt++] = make_int2(e, off + s);
            off += c;
        }
        g_offsets[NEXP] = off;
        g_num_tiles = nt;
    }
}

// position assignment via ballot aggregation (16 blocks x 256; 8 atomics/block)
__global__ void k_pos() {
    __shared__ int warp_cnt[8][NEXP];
    __shared__ int warp_base[8][NEXP];
    int t = blockIdx.x * blockDim.x + threadIdx.x;
    int e = g_expert[t];
    int lane = threadIdx.x & 31, w = threadIdx.x >> 5;
    int lane_rank = 0;
#pragma unroll
    for (int ee = 0; ee < NEXP; ee++) {
        unsigned m = __ballot_sync(0xFFFFFFFFu, e == ee);
        if (e == ee) lane_rank = __popc(m & ((1u << lane) - 1));
        if (lane == 0) warp_cnt[w][ee] = __popc(m);
    }
    __syncthreads();
    if (threadIdx.x < NEXP) {
        int ee = threadIdx.x;
        int sum = 0, pre[8];
#pragma unroll
        for (int ww = 0; ww < 8; ww++) { pre[ww] = sum; sum += warp_cnt[ww][ee]; }
        int base = atomicAdd(&g_fill[ee], sum);
#pragma unroll
        for (int ww = 0; ww < 8; ww++) warp_base[ww][ee] = base + pre[ww];
    }
    __syncthreads();
    int pos = g_offsets[e] + warp_base[w][e] + lane_rank;
    g_sorted[pos] = t;
}

// permute fp16 tokens into expert-sorted order (8MB read + 8MB write)
__global__ void k_copy_x() {
    int p = blockIdx.x;
    int tok = g_sorted[p];
    const uint4* src = (const uint4*)(g_xh + (size_t)tok * DIM);
    uint4* dst = (uint4*)(g_xs + (size_t)p * DIM);
    dst[threadIdx.x] = src[threadIdx.x];
}

// grid-stride weight conversion
__global__ void k_prep_w(const float* __restrict__ ew) {
    const size_t total = (size_t)NEXP * DIM * DIM / 4;   // float4 count
    size_t stride = (size_t)gridDim.x * blockDim.x;
    for (size_t i4 = (size_t)blockIdx.x * blockDim.x + threadIdx.x; i4 < total; i4 += stride) {
        float4 v = ((const float4*)ew)[i4];
        union { __half h[4]; uint2 u; } h4;
        h4.h[0] = __float2half(v.x);
        h4.h[1] = __float2half(v.y);
        h4.h[2] = __float2half(v.z);
        h4.h[3] = __float2half(v.w);
        ((uint2*)g_wh)[i4] = h4.u;
    }
}

// ---------------- persistent mma.sync grouped GEMM (R8 structure, sorted A) ----------------
__global__ void __launch_bounds__(256, 2) k_gemm(const float* __restrict__ eb,
                                                 float* __restrict__ out) {
    extern __shared__ char smem[];
    uint32_t sb = smem_u32(smem);
    __shared__ int   s_job;
    __shared__ int   s_tok[TM];
    __shared__ float s_w[TM];

    int tid = threadIdx.x;
    int wid = tid >> 5;
    int lane = tid & 31;
    int warp_m = wid & 3;    // 4 slabs of 32 rows
    int warp_n = wid >> 2;   // 2 slabs of 64 cols

    uint32_t aoff = (uint32_t)((warp_m * 32 + (lane & 15)) * SROW + (lane >> 4) * 16);
    uint32_t boff = (uint32_t)((warp_n * 64 + ((lane >> 4) << 3) + (lane & 7)) * SROW
                               + ((lane >> 3) & 1) * 16);

    for (;;) {
        if (tid == 0) s_job = atomicAdd(&g_ticket, 1);
        __syncthreads();
        int job = s_job;
        int njobs = g_num_tiles * (DIM / TN);
        if (job >= njobs) return;

        int nb   = job & 7;          // DIM/TN == 8
        int tile = job >> 3;
        int2 td = g_tiles[tile];
        int e = td.x, row0 = td.y;
        int segend = g_offsets[e + 1];
        int n0 = nb * TN;

        if (tid < TM) {
            int r = row0 + tid;
            int tok = (r < segend) ? g_sorted[r] : -1;
            s_tok[tid] = tok;
            s_w[tid]   = (tok >= 0) ? g_weight[tok] : 0.f;
        }

        float c[2][8][4];
#pragma unroll
        for (int mt = 0; mt < 2; mt++)
#pragma unroll
            for (int nt = 0; nt < 8; nt++)
#pragma unroll
                for (int j = 0; j < 4; j++) c[mt][nt][j] = 0.f;

        // 2 mats x 128 rows x 8 segs = 2048 cp.async / 256 thr = 8 each (R8 spread mapping)
        auto issue = [&](int ch, int st) {
            int k0 = ch * KC;
            uint32_t stbase = sb + st * STAGE_BYTES;
#pragma unroll
            for (int i = 0; i < 8; i++) {
                int idx = i * 256 + tid;
                int mat = idx >> 10;
                int w   = idx & 1023;
                int row = w >> 3;
                int seg = w & 7;
                uint32_t dst = stbase + mat * MAT_BYTES + row * SROW + seg * 16;
                const __half* src;
                if (mat == 0) src = g_xs + (size_t)(row0 + row) * DIM + k0 + seg * 8;
                else          src = g_wh + (size_t)(e * DIM + n0 + row) * DIM + k0 + seg * 8;
                CP_ASYNC16(dst, src);
            }
            CP_COMMIT();
        };

        issue(0, 0); issue(1, 1); issue(2, 2);

        for (int ch = 0; ch < NCH; ch++) {
            int st = ch % NSTAGE;
            int rem = NCH - 1 - ch;
            if (rem >= 2) CP_WAIT(2);
            else if (rem == 1) CP_WAIT(1);
            else CP_WAIT(0);
            __syncthreads();

            uint32_t sA = sb + st * STAGE_BYTES;
            uint32_t sB = sA + MAT_BYTES;
#pragma unroll
            for (int ks = 0; ks < 4; ks++) {
                uint32_t kb = ks * 32;           // 16 elems * 2B
                uint32_t a[2][4], b[8][2];
#pragma unroll
                for (int mt = 0; mt < 2; mt++) {
                    uint32_t aa = sA + mt * (16 * SROW) + aoff + kb;
                    LDSM_X4(a[mt][0], a[mt][1], a[mt][2], a[mt][3], aa);
                }
#pragma unroll
                for (int p = 0; p < 4; p++) {
                    uint32_t ba = sB + p * (16 * SROW) + boff + kb;
                    LDSM_X4(b[p * 2][0], b[p * 2][1], b[p * 2 + 1][0], b[p * 2 + 1][1], ba);
                }
#pragma unroll
                for (int mt = 0; mt < 2; mt++)
#pragma unroll
                    for (int nt = 0; nt < 8; nt++)
                        MMA_F16(c[mt][nt], a[mt], b[nt]);
            }
            __syncthreads();
            if (ch + NSTAGE < NCH) issue(ch + NSTAGE, st);
        }

        // ---------------- epilogue ----------------
        int ncol_base = n0 + warp_n * 64 + (lane & 3) * 2;
#pragma unroll
        for (int mt = 0; mt < 2; mt++) {
#pragma unroll
            for (int half = 0; half < 2; half++) {
                int rl = warp_m * 32 + mt * 16 + (lane >> 2) + half * 8;
                int tok = s_tok[rl];
                if (tok < 0) continue;
                float wt = s_w[rl];
                float* orow = out + (size_t)tok * DIM;
#pragma unroll
                for (int nt = 0; nt < 8; nt++) {
                    int nc = ncol_base + nt * 8;
                    float2 b2 = *(const float2*)(eb + (size_t)e * DIM + nc);
                    float2 r2;
                    r2.x = (c[mt][nt][half * 2 + 0] + b2.x) * wt;
                    r2.y = (c[mt][nt][half * 2 + 1] + b2.y) * wt;
                    *(float2*)(orow + nc) = r2;
                }
            }
        }
        __syncthreads();   // protect s_job / s_tok before next job
    }
}

// ---------------- launch ----------------
extern "C" void kernel_launch(void* const* d_in, const int* in_sizes, int n_in,
                              void* d_out, int out_size) {
    const float* x  = (const float*)d_in[0];
    const float* rw = (const float*)d_in[1];
    const float* rb = (const float*)d_in[2];
    const float* ew = (const float*)d_in[3];
    const float* eb = (const float*)d_in[4];
    float* out = (float*)d_out;

    cudaFuncSetAttribute(k_gemm, cudaFuncAttributeMaxDynamicSharedMemorySize, SMEM_BYTES);

    k_router<<<(NTOK * 32) / 256, 256>>>(x, rw, rb);
    k_histscan<<<1, 1024>>>();
    k_pos<<<NTOK / 256, 256>>>();
    k_copy_x<<<NTOK, 128>>>();
    k_prep_w<<<8 * 148, 256>>>(ew);
    k_gemm<<<GEMM_CTAS, 256, SMEM_BYTES>>>(eb, out);
}

// round 15
// speedup vs baseline: 1.7217x; 1.0114x over previous
#include <cuda_runtime.h>
#include <cuda_bf16.h>
#include <cuda_fp16.h>
#include <math.h>
#include <stdint.h>

#define NTOK 4096
#define DIM  1024
#define NEXP 8
#define TM   128
#define TN   128
#define KC   64                      // K elems per pipeline chunk
#define NCH  (DIM / KC)              // 16
#define MAX_TILES (NTOK / TM + NEXP) // 40

// padded SMEM row: 64 fp16 data + 8 pad = 72 elems = 144 bytes (conflict-free)
#define SROW 144
#define MAT_BYTES   (128 * SROW)         // 18432
#define STAGE_BYTES (2 * MAT_BYTES)      // 36864 (A, B)
#define NSTAGE 3
#define SMEM_BYTES  (NSTAGE * STAGE_BYTES)   // 110592

#define GEMM_CTAS (2 * 148)

// ---------------- device scratch ----------------
__device__ float g_weight[NTOK];
__device__ int   g_expert[NTOK];
__device__ int   g_fill[NEXP];
__device__ int   g_offsets[NEXP + 1];
__device__ int   g_sorted[NTOK];
__device__ int2  g_tiles[MAX_TILES];
__device__ int   g_num_tiles;
__device__ int   g_ticket;
__device__ __half g_xh[NTOK * DIM];          // token-indexed fp16 x (from router)
__device__ __half g_xs[(NTOK + TM) * DIM];   // expert-sorted fp16 x (GEMM A operand)
__device__ __half g_wh[NEXP * DIM * DIM];

// ---------------- PTX helpers (base compute_103 only) ----------------
__device__ __forceinline__ uint32_t smem_u32(const void* p) {
    uint32_t a;
    asm("{ .reg .u64 t; cvta.to.shared.u64 t, %1; cvt.u32.u64 %0, t; }" : "=r"(a) : "l"(p));
    return a;
}
#define CP_ASYNC16(dst, src) \
    asm volatile("cp.async.cg.shared.global [%0], [%1], 16;" :: "r"(dst), "l"(src) : "memory")
#define CP_COMMIT() asm volatile("cp.async.commit_group;" ::: "memory")
#define CP_WAIT(n)  asm volatile("cp.async.wait_group %0;" :: "n"(n) : "memory")

#define LDSM_X4(r0, r1, r2, r3, addr) \
    asm volatile("ldmatrix.sync.aligned.m8n8.x4.shared.b16 {%0,%1,%2,%3}, [%4];" \
                 : "=r"(r0), "=r"(r1), "=r"(r2), "=r"(r3) : "r"(addr))

#define MMA_F16(c, a, b) \
    asm volatile("mma.sync.aligned.m16n8k16.row.col.f32.f16.f16.f32 " \
                 "{%0,%1,%2,%3}, {%4,%5,%6,%7}, {%8,%9}, {%0,%1,%2,%3};" \
                 : "+f"((c)[0]), "+f"((c)[1]), "+f"((c)[2]), "+f"((c)[3]) \
                 : "r"((a)[0]), "r"((a)[1]), "r"((a)[2]), "r"((a)[3]), \
                   "r"((b)[0]), "r"((b)[1]))

// ---------------- small kernels ----------------
// router: expert + weight per token, AND fp32->fp16 conversion of x (fused)
__global__ void k_router(const float* __restrict__ x,
                         const float* __restrict__ rw,
                         const float* __restrict__ rb) {
    int warp = (blockIdx.x * blockDim.x + threadIdx.x) >> 5;
    int lane = threadIdx.x & 31;
    if (warp >= NTOK) return;
    const float4* xr = (const float4*)(x + (size_t)warp * DIM);
    uint2* xo = (uint2*)(g_xh + (size_t)warp * DIM);
    float acc[NEXP];
#pragma unroll
    for (int e = 0; e < NEXP; e++) acc[e] = 0.f;
#pragma unroll
    for (int it = 0; it < DIM / 4 / 32; it++) {
        int i = lane + it * 32;
        float4 xv = xr[i];
        union { __half h[4]; uint2 u; } hv;
        hv.h[0] = __float2half(xv.x);
        hv.h[1] = __float2half(xv.y);
        hv.h[2] = __float2half(xv.z);
        hv.h[3] = __float2half(xv.w);
        xo[i] = hv.u;
#pragma unroll
        for (int e = 0; e < NEXP; e++) {
            float4 wv = ((const float4*)(rw + e * DIM))[i];
            acc[e] += xv.x * wv.x + xv.y * wv.y + xv.z * wv.z + xv.w * wv.w;
        }
    }
#pragma unroll
    for (int e = 0; e < NEXP; e++)
#pragma unroll
        for (int o = 16; o > 0; o >>= 1)
            acc[e] += __shfl_xor_sync(0xFFFFFFFFu, acc[e], o);
    if (lane == 0) {
        float best = -1e30f; int bi = 0;
#pragma unroll
        for (int e = 0; e < NEXP; e++) {
            float l = acc[e] + rb[e];
            if (l > best) { best = l; bi = e; }
        }
        float s = 0.f;
#pragma unroll
        for (int e = 0; e < NEXP; e++) s += expf(acc[e] + rb[e] - best);
        g_weight[warp] = 1.f / s;
        g_expert[warp] = bi;
    }
}

// fused init + histogram + scan + tile list (single block, 1024 threads)
__global__ void k_histscan() {
    __shared__ int h[NEXP];
    int tid = threadIdx.x;
    if (tid < NEXP) { h[tid] = 0; g_fill[tid] = 0; }
    if (tid == 0) g_ticket = 0;
    __syncthreads();
#pragma unroll
    for (int i = 0; i < NTOK / 1024; i++)
        atomicAdd(&h[g_expert[tid + i * 1024]], 1);
    __syncthreads();
    if (tid == 0) {
        int off = 0, nt = 0;
        for (int e = 0; e < NEXP; e++) {
            g_offsets[e] = off;
            int c = h[e];
            for (int s = 0; s < c; s += TM) g_tiles[nt++] = make_int2(e, off + s);
            off += c;
        }
        g_offsets[NEXP] = off;
        g_num_tiles = nt;
    }
}

// position assignment via ballot aggregation (16 blocks x 256; 8 atomics/block)
__global__ void k_pos() {
    __shared__ int warp_cnt[8][NEXP];
    __shared__ int warp_base[8][NEXP];
    int t = blockIdx.x * blockDim.x + threadIdx.x;
    int e = g_expert[t];
    int lane = threadIdx.x & 31, w = threadIdx.x >> 5;
    int lane_rank = 0;
#pragma unroll
    for (int ee = 0; ee < NEXP; ee++) {
        unsigned m = __ballot_sync(0xFFFFFFFFu, e == ee);
        if (e == ee) lane_rank = __popc(m & ((1u << lane) - 1));
        if (lane == 0) warp_cnt[w][ee] = __popc(m);
    }
    __syncthreads();
    if (threadIdx.x < NEXP) {
        int ee = threadIdx.x;
        int sum = 0, pre[8];
#pragma unroll
        for (int ww = 0; ww < 8; ww++) { pre[ww] = sum; sum += warp_cnt[ww][ee]; }
        int base = atomicAdd(&g_fill[ee], sum);
#pragma unroll
        for (int ww = 0; ww < 8; ww++) warp_base[ww][ee] = base + pre[ww];
    }
    __syncthreads();
    int pos = g_offsets[e] + warp_base[w][e] + lane_rank;
    g_sorted[pos] = t;
}

// permute fp16 tokens into expert-sorted order (8MB read + 8MB write)
__global__ void k_copy_x() {
    int p = blockIdx.x;
    int tok = g_sorted[p];
    const uint4* src = (const uint4*)(g_xh + (size_t)tok * DIM);
    uint4* dst = (uint4*)(g_xs + (size_t)p * DIM);
    dst[threadIdx.x] = src[threadIdx.x];
}

// grid-stride weight conversion (forked stream, overlapped with routing chain)
__global__ void k_prep_w(const float* __restrict__ ew) {
    const size_t total = (size_t)NEXP * DIM * DIM / 4;   // float4 count
    size_t stride = (size_t)gridDim.x * blockDim.x;
    for (size_t i4 = (size_t)blockIdx.x * blockDim.x + threadIdx.x; i4 < total; i4 += stride) {
        float4 v = ((const float4*)ew)[i4];
        union { __half h[4]; uint2 u; } h4;
        h4.h[0] = __float2half(v.x);
        h4.h[1] = __float2half(v.y);
        h4.h[2] = __float2half(v.z);
        h4.h[3] = __float2half(v.w);
        ((uint2*)g_wh)[i4] = h4.u;
    }
}

// ---------------- persistent mma.sync grouped GEMM (R8 structure, sorted A) ----------------
__global__ void __launch_bounds__(256, 2) k_gemm(const float* __restrict__ eb,
                                                 float* __restrict__ out) {
    extern __shared__ char smem[];
    uint32_t sb = smem_u32(smem);
    __shared__ int   s_job;
    __shared__ int   s_tok[TM];
    __shared__ float s_w[TM];

    int tid = threadIdx.x;
    int wid = tid >> 5;
    int lane = tid & 31;
    int warp_m = wid & 3;    // 4 slabs of 32 rows
    int warp_n = wid >> 2;   // 2 slabs of 64 cols

    uint32_t aoff = (uint32_t)((warp_m * 32 + (lane & 15)) * SROW + (lane >> 4) * 16);
    uint32_t boff = (uint32_t)((warp_n * 64 + ((lane >> 4) << 3) + (lane & 7)) * SROW
                               + ((lane >> 3) & 1) * 16);

    for (;;) {
        if (tid == 0) s_job = atomicAdd(&g_ticket, 1);
        __syncthreads();
        int job = s_job;
        int njobs = g_num_tiles * (DIM / TN);
        if (job >= njobs) return;

        int nb   = job & 7;          // DIM/TN == 8
        int tile = job >> 3;
        int2 td = g_tiles[tile];
        int e = td.x, row0 = td.y;
        int segend = g_offsets[e + 1];
        int n0 = nb * TN;

        if (tid < TM) {
            int r = row0 + tid;
            int tok = (r < segend) ? g_sorted[r] : -1;
            s_tok[tid] = tok;
            s_w[tid]   = (tok >= 0) ? g_weight[tok] : 0.f;
        }

        float c[2][8][4];
#pragma unroll
        for (int mt = 0; mt < 2; mt++)
#pragma unroll
            for (int nt = 0; nt < 8; nt++)
#pragma unroll
                for (int j = 0; j < 4; j++) c[mt][nt][j] = 0.f;

        // 2 mats x 128 rows x 8 segs = 2048 cp.async / 256 thr = 8 each (R8 spread mapping)
        auto issue = [&](int ch, int st) {
            int k0 = ch * KC;
            uint32_t stbase = sb + st * STAGE_BYTES;
#pragma unroll
            for (int i = 0; i < 8; i++) {
                int idx = i * 256 + tid;
                int mat = idx >> 10;
                int w   = idx & 1023;
                int row = w >> 3;
                int seg = w & 7;
                uint32_t dst = stbase + mat * MAT_BYTES + row * SROW + seg * 16;
                const __half* src;
                if (mat == 0) src = g_xs + (size_t)(row0 + row) * DIM + k0 + seg * 8;
                else          src = g_wh + (size_t)(e * DIM + n0 + row) * DIM + k0 + seg * 8;
                CP_ASYNC16(dst, src);
            }
            CP_COMMIT();
        };

        issue(0, 0); issue(1, 1); issue(2, 2);

        for (int ch = 0; ch < NCH; ch++) {
            int st = ch % NSTAGE;
            int rem = NCH - 1 - ch;
            if (rem >= 2) CP_WAIT(2);
            else if (rem == 1) CP_WAIT(1);
            else CP_WAIT(0);
            __syncthreads();

            uint32_t sA = sb + st * STAGE_BYTES;
            uint32_t sB = sA + MAT_BYTES;
#pragma unroll
            for (int ks = 0; ks < 4; ks++) {
                uint32_t kb = ks * 32;           // 16 elems * 2B
                uint32_t a[2][4], b[8][2];
#pragma unroll
                for (int mt = 0; mt < 2; mt++) {
                    uint32_t aa = sA + mt * (16 * SROW) + aoff + kb;
                    LDSM_X4(a[mt][0], a[mt][1], a[mt][2], a[mt][3], aa);
                }
#pragma unroll
                for (int p = 0; p < 4; p++) {
                    uint32_t ba = sB + p * (16 * SROW) + boff + kb;
                    LDSM_X4(b[p * 2][0], b[p * 2][1], b[p * 2 + 1][0], b[p * 2 + 1][1], ba);
                }
#pragma unroll
                for (int mt = 0; mt < 2; mt++)
#pragma unroll
                    for (int nt = 0; nt < 8; nt++)
                        MMA_F16(c[mt][nt], a[mt], b[nt]);
            }
            __syncthreads();
            if (ch + NSTAGE < NCH) issue(ch + NSTAGE, st);
        }

        // ---------------- epilogue ----------------
        int ncol_base = n0 + warp_n * 64 + (lane & 3) * 2;
#pragma unroll
        for (int mt = 0; mt < 2; mt++) {
#pragma unroll
            for (int half = 0; half < 2; half++) {
                int rl = warp_m * 32 + mt * 16 + (lane >> 2) + half * 8;
                int tok = s_tok[rl];
                if (tok < 0) continue;
                float wt = s_w[rl];
                float* orow = out + (size_t)tok * DIM;
#pragma unroll
                for (int nt = 0; nt < 8; nt++) {
                    int nc = ncol_base + nt * 8;
                    float2 b2 = *(const float2*)(eb + (size_t)e * DIM + nc);
                    float2 r2;
                    r2.x = (c[mt][nt][half * 2 + 0] + b2.x) * wt;
                    r2.y = (c[mt][nt][half * 2 + 1] + b2.y) * wt;
                    *(float2*)(orow + nc) = r2;
                }
            }
        }
        __syncthreads();   // protect s_job / s_tok before next job
    }
}

// ---------------- launch ----------------
extern "C" void kernel_launch(void* const* d_in, const int* in_sizes, int n_in,
                              void* d_out, int out_size) {
    const float* x  = (const float*)d_in[0];
    const float* rw = (const float*)d_in[1];
    const float* rb = (const float*)d_in[2];
    const float* ew = (const float*)d_in[3];
    const float* eb = (const float*)d_in[4];
    float* out = (float*)d_out;

    // one-time host resources (resource cache, not a work guard — identical work per call)
    static cudaStream_t s2 = nullptr;
    static cudaEvent_t ev_fork = nullptr, ev_join = nullptr;
    if (s2 == nullptr) {
        cudaStreamCreateWithFlags(&s2, cudaStreamNonBlocking);
        cudaEventCreateWithFlags(&ev_fork, cudaEventDisableTiming);
        cudaEventCreateWithFlags(&ev_join, cudaEventDisableTiming);
        cudaFuncSetAttribute(k_gemm, cudaFuncAttributeMaxDynamicSharedMemorySize, SMEM_BYTES);
    }

    // fork: prep_w concurrent with the routing chain
    cudaEventRecord(ev_fork, 0);
    cudaStreamWaitEvent(s2, ev_fork, 0);
    k_prep_w<<<8 * 148, 256, 0, s2>>>(ew);
    cudaEventRecord(ev_join, s2);

    k_router<<<(NTOK * 32) / 256, 256>>>(x, rw, rb);
    k_histscan<<<1, 1024>>>();
    k_pos<<<NTOK / 256, 256>>>();
    k_copy_x<<<NTOK, 128>>>();

    // join before GEMM consumes g_wh
    cudaStreamWaitEvent(0, ev_join, 0);
    k_gemm<<<GEMM_CTAS, 256, SMEM_BYTES>>>(eb, out);
}

// round 17
// speedup vs baseline: 2.0656x; 1.1998x over previous
#include <cuda_runtime.h>
#include <cuda_bf16.h>
#include <cuda_fp16.h>
#include <math.h>
#include <stdint.h>

#define NTOK 4096
#define DIM  1024
#define NEXP 8
#define TM   128
#define TN   128
#define KC   64                      // K elems per pipeline chunk
#define NCH  (DIM / KC)              // 16
#define MAX_TILES (NTOK / TM + NEXP) // 40

// padded SMEM row: 64 fp16 data + 8 pad = 72 elems = 144 bytes (conflict-free)
#define SROW 144
#define MAT_BYTES   (128 * SROW)         // 18432
#define STAGE_BYTES (2 * MAT_BYTES)      // 36864 (A, B)
#define NSTAGE 3
#define SMEM_BYTES  (NSTAGE * STAGE_BYTES)   // 110592

#define GEMM_CTAS (2 * 148)
#define RT_TPB 16                    // tokens per router block (512 threads)

// ---------------- device scratch ----------------
__device__ int   g_fill[NEXP];
__device__ int   g_cnt[NEXP];
__device__ int   g_tokid[NEXP * NTOK];
__device__ float g_wtp[NEXP * NTOK];
__device__ int2  g_tiles[MAX_TILES];
__device__ int   g_num_tiles;
__device__ int   g_ticket;
__device__ __half g_xs[(size_t)NEXP * NTOK * DIM];  // capacity-padded expert segments
__device__ __half g_wh[NEXP * DIM * DIM];

// ---------------- PTX helpers (base compute_103 only) ----------------
__device__ __forceinline__ uint32_t smem_u32(const void* p) {
    uint32_t a;
    asm("{ .reg .u64 t; cvta.to.shared.u64 t, %1; cvt.u32.u64 %0, t; }" : "=r"(a) : "l"(p));
    return a;
}
#define CP_ASYNC16(dst, src) \
    asm volatile("cp.async.cg.shared.global [%0], [%1], 16;" :: "r"(dst), "l"(src) : "memory")
#define CP_COMMIT() asm volatile("cp.async.commit_group;" ::: "memory")
#define CP_WAIT(n)  asm volatile("cp.async.wait_group %0;" :: "n"(n) : "memory")

#define LDSM_X4(r0, r1, r2, r3, addr) \
    asm volatile("ldmatrix.sync.aligned.m8n8.x4.shared.b16 {%0,%1,%2,%3}, [%4];" \
                 : "=r"(r0), "=r"(r1), "=r"(r2), "=r"(r3) : "r"(addr))

#define MMA_F16(c, a, b) \
    asm volatile("mma.sync.aligned.m16n8k16.row.col.f32.f16.f16.f32 " \
                 "{%0,%1,%2,%3}, {%4,%5,%6,%7}, {%8,%9}, {%0,%1,%2,%3};" \
                 : "+f"((c)[0]), "+f"((c)[1]), "+f"((c)[2]), "+f"((c)[3]) \
                 : "r"((a)[0]), "r"((a)[1]), "r"((a)[2]), "r"((a)[3]), \
                   "r"((b)[0]), "r"((b)[1]))

// ---------------- small kernels ----------------
__global__ void k_init() {
    if (threadIdx.x < NEXP) g_fill[threadIdx.x] = 0;
}

// router: routes token, claims slot in its expert segment, writes fp16 row there
__global__ void __launch_bounds__(RT_TPB * 32) k_router(const float* __restrict__ x,
                                                        const float* __restrict__ rw,
                                                        const float* __restrict__ rb) {
    __shared__ int   s_exp[RT_TPB];
    __shared__ float s_wt[RT_TPB];
    __shared__ int   s_pos[RT_TPB];
    int wid = threadIdx.x >> 5;
    int lane = threadIdx.x & 31;
    int tok = blockIdx.x * RT_TPB + wid;

    const float4* xr = (const float4*)(x + (size_t)tok * DIM);
    uint2 hv[8];                     // this lane's fp16 row chunk (kept in regs)
    float acc[NEXP];
#pragma unroll
    for (int e = 0; e < NEXP; e++) acc[e] = 0.f;
#pragma unroll
    for (int it = 0; it < 8; it++) {
        int i = lane + it * 32;
        float4 xv = xr[i];
        union { __half h[4]; uint2 u; } cv;
        cv.h[0] = __float2half(xv.x);
        cv.h[1] = __float2half(xv.y);
        cv.h[2] = __float2half(xv.z);
        cv.h[3] = __float2half(xv.w);
        hv[it] = cv.u;
#pragma unroll
        for (int e = 0; e < NEXP; e++) {
            float4 wv = ((const float4*)(rw + e * DIM))[i];
            acc[e] += xv.x * wv.x + xv.y * wv.y + xv.z * wv.z + xv.w * wv.w;
        }
    }
#pragma unroll
    for (int e = 0; e < NEXP; e++)
#pragma unroll
        for (int o = 16; o > 0; o >>= 1)
            acc[e] += __shfl_xor_sync(0xFFFFFFFFu, acc[e], o);
    if (lane == 0) {
        float best = -1e30f; int bi = 0;
#pragma unroll
        for (int e = 0; e < NEXP; e++) {
            float l = acc[e] + rb[e];
            if (l > best) { best = l; bi = e; }
        }
        float s = 0.f;
#pragma unroll
        for (int e = 0; e < NEXP; e++) s += expf(acc[e] + rb[e] - best);
        s_exp[wid] = bi;
        s_wt[wid]  = 1.f / s;
    }
    __syncthreads();

    // slot claim: first RT_TPB lanes of warp 0, match_any leader election
    if (threadIdx.x < RT_TPB) {
        const unsigned mask = (1u << RT_TPB) - 1u;
        int e = s_exp[threadIdx.x];
        unsigned m = __match_any_sync(mask, e);
        int leader = __ffs(m) - 1;
        int rank = __popc(m & ((1u << threadIdx.x) - 1u));
        int base = 0;
        if ((int)threadIdx.x == leader) base = atomicAdd(&g_fill[e], __popc(m));
        base = __shfl_sync(mask, base, leader);
        s_pos[threadIdx.x] = base + rank;
    }
    __syncthreads();

    int e = s_exp[wid];
    int pos = s_pos[wid];
    if (pos < NTOK) {   // always true (≤ NTOK tokens total); guards the write anyway
        uint2* xo = (uint2*)(g_xs + ((size_t)e * NTOK + pos) * DIM);
#pragma unroll
        for (int it = 0; it < 8; it++) xo[lane + it * 32] = hv[it];
        if (lane == 0) {
            g_tokid[e * NTOK + pos] = tok;
            g_wtp[e * NTOK + pos]   = s_wt[wid];
        }
    }
}

// tile list from final counts (1 warp)
__global__ void k_tiles() {
    if (threadIdx.x == 0) {
        int nt = 0;
        for (int e = 0; e < NEXP; e++) {
            int c = g_fill[e];
            g_cnt[e] = c;
            for (int s = 0; s < c; s += TM) g_tiles[nt++] = make_int2(e, s);
        }
        g_num_tiles = nt;
        g_ticket = 0;
    }
}

// grid-stride weight conversion (forked stream, overlapped with router)
__global__ void k_prep_w(const float* __restrict__ ew) {
    const size_t total = (size_t)NEXP * DIM * DIM / 4;   // float4 count
    size_t stride = (size_t)gridDim.x * blockDim.x;
    for (size_t i4 = (size_t)blockIdx.x * blockDim.x + threadIdx.x; i4 < total; i4 += stride) {
        float4 v = ((const float4*)ew)[i4];
        union { __half h[4]; uint2 u; } h4;
        h4.h[0] = __float2half(v.x);
        h4.h[1] = __float2half(v.y);
        h4.h[2] = __float2half(v.z);
        h4.h[3] = __float2half(v.w);
        ((uint2*)g_wh)[i4] = h4.u;
    }
}

// ---------------- persistent mma.sync grouped GEMM (R14 structure, padded segments) ----------------
__global__ void __launch_bounds__(256, 2) k_gemm(const float* __restrict__ eb,
                                                 float* __restrict__ out) {
    extern __shared__ char smem[];
    uint32_t sb = smem_u32(smem);
    __shared__ int   s_job;
    __shared__ int   s_tok[TM];
    __shared__ float s_w[TM];

    int tid = threadIdx.x;
    int wid = tid >> 5;
    int lane = tid & 31;
    int warp_m = wid & 3;    // 4 slabs of 32 rows
    int warp_n = wid >> 2;   // 2 slabs of 64 cols

    uint32_t aoff = (uint32_t)((warp_m * 32 + (lane & 15)) * SROW + (lane >> 4) * 16);
    uint32_t boff = (uint32_t)((warp_n * 64 + ((lane >> 4) << 3) + (lane & 7)) * SROW
                               + ((lane >> 3) & 1) * 16);

    for (;;) {
        if (tid == 0) s_job = atomicAdd(&g_ticket, 1);
        __syncthreads();
        int job = s_job;
        int njobs = g_num_tiles * (DIM / TN);
        if (job >= njobs) return;

        int nb   = job & 7;          // DIM/TN == 8
        int tile = job >> 3;
        int2 td = g_tiles[tile];
        int e = td.x, m0 = td.y;
        int cnt = g_cnt[e];
        int n0 = nb * TN;

        if (tid < TM) {
            int r = m0 + tid;
            bool v = (r < cnt);
            s_tok[tid] = v ? g_tokid[e * NTOK + r] : -1;
            s_w[tid]   = v ? g_wtp[e * NTOK + r] : 0.f;
        }

        float c[2][8][4];
#pragma unroll
        for (int mt = 0; mt < 2; mt++)
#pragma unroll
            for (int nt = 0; nt < 8; nt++)
#pragma unroll
                for (int j = 0; j < 4; j++) c[mt][nt][j] = 0.f;

        // 2 mats x 128 rows x 8 segs = 2048 cp.async / 256 thr = 8 each (R8 spread mapping)
        auto issue = [&](int ch, int st) {
            int k0 = ch * KC;
            uint32_t stbase = sb + st * STAGE_BYTES;
#pragma unroll
            for (int i = 0; i < 8; i++) {
                int idx = i * 256 + tid;
                int mat = idx >> 10;
                int w   = idx & 1023;
                int row = w >> 3;
                int seg = w & 7;
                uint32_t dst = stbase + mat * MAT_BYTES + row * SROW + seg * 16;
                const __half* src;
                if (mat == 0) src = g_xs + ((size_t)e * NTOK + m0 + row) * DIM + k0 + seg * 8;
                else          src = g_wh + (size_t)(e * DIM + n0 + row) * DIM + k0 + seg * 8;
                CP_ASYNC16(dst, src);
            }
            CP_COMMIT();
        };

        issue(0, 0); issue(1, 1); issue(2, 2);

        for (int ch = 0; ch < NCH; ch++) {
            int st = ch % NSTAGE;
            int rem = NCH - 1 - ch;
            if (rem >= 2) CP_WAIT(2);
            else if (rem == 1) CP_WAIT(1);
            else CP_WAIT(0);
            __syncthreads();

            uint32_t sA = sb + st * STAGE_BYTES;
            uint32_t sB = sA + MAT_BYTES;
#pragma unroll
            for (int ks = 0; ks < 4; ks++) {
                uint32_t kb = ks * 32;           // 16 elems * 2B
                uint32_t a[2][4], b[8][2];
#pragma unroll
                for (int mt = 0; mt < 2; mt++) {
                    uint32_t aa = sA + mt * (16 * SROW) + aoff + kb;
                    LDSM_X4(a[mt][0], a[mt][1], a[mt][2], a[mt][3], aa);
                }
#pragma unroll
                for (int p = 0; p < 4; p++) {
                    uint32_t ba = sB + p * (16 * SROW) + boff + kb;
                    LDSM_X4(b[p * 2][0], b[p * 2][1], b[p * 2 + 1][0], b[p * 2 + 1][1], ba);
                }
#pragma unroll
                for (int mt = 0; mt < 2; mt++)
#pragma unroll
                    for (int nt = 0; nt < 8; nt++)
                        MMA_F16(c[mt][nt], a[mt], b[nt]);
            }
            __syncthreads();
            if (ch + NSTAGE < NCH) issue(ch + NSTAGE, st);
        }

        // ---------------- epilogue ----------------
        int ncol_base = n0 + warp_n * 64 + (lane & 3) * 2;
#pragma unroll
        for (int mt = 0; mt < 2; mt++) {
#pragma unroll
            for (int half = 0; half < 2; half++) {
                int rl = warp_m * 32 + mt * 16 + (lane >> 2) + half * 8;
                int tok = s_tok[rl];
                if (tok < 0) continue;
                float wt = s_w[rl];
                float* orow = out + (size_t)tok * DIM;
#pragma unroll
                for (int nt = 0; nt < 8; nt++) {
                    int nc = ncol_base + nt * 8;
                    float2 b2 = *(const float2*)(eb + (size_t)e * DIM + nc);
                    float2 r2;
                    r2.x = (c[mt][nt][half * 2 + 0] + b2.x) * wt;
                    r2.y = (c[mt][nt][half * 2 + 1] + b2.y) * wt;
                    *(float2*)(orow + nc) = r2;
                }
            }
        }
        __syncthreads();   // protect s_job / s_tok before next job
    }
}

// ---------------- launch ----------------
extern "C" void kernel_launch(void* const* d_in, const int* in_sizes, int n_in,
                              void* d_out, int out_size) {
    const float* x  = (const float*)d_in[0];
    const float* rw = (const float*)d_in[1];
    const float* rb = (const float*)d_in[2];
    const float* ew = (const float*)d_in[3];
    const float* eb = (const float*)d_in[4];
    float* out = (float*)d_out;

    // one-time host resources (resource cache, not a work guard — identical work per call)
    static cudaStream_t s2 = nullptr;
    static cudaEvent_t ev_fork = nullptr, ev_join = nullptr;
    if (s2 == nullptr) {
        cudaStreamCreateWithFlags(&s2, cudaStreamNonBlocking);
        cudaEventCreateWithFlags(&ev_fork, cudaEventDisableTiming);
        cudaEventCreateWithFlags(&ev_join, cudaEventDisableTiming);
        cudaFuncSetAttribute(k_gemm, cudaFuncAttributeMaxDynamicSharedMemorySize, SMEM_BYTES);
    }

    k_init<<<1, 32>>>();

    // fork: prep_w concurrent with routing
    cudaEventRecord(ev_fork, 0);
    cudaStreamWaitEvent(s2, ev_fork, 0);
    k_prep_w<<<8 * 148, 256, 0, s2>>>(ew);
    cudaEventRecord(ev_join, s2);

    k_router<<<NTOK / RT_TPB, RT_TPB * 32>>>(x, rw, rb);
    k_tiles<<<1, 32>>>();

    // join before GEMM consumes g_wh
    cudaStreamWaitEvent(0, ev_join, 0);
    k_gemm<<<GEMM_CTAS, 256, SMEM_BYTES>>>(eb, out);
}